// round 1
// baseline (speedup 1.0000x reference)
#include <cuda_runtime.h>
#include <cuda_bf16.h>
#include <math.h>

// ---------------------------------------------------------------------------
// DiT block, fp32 baseline.
//   B=2, N=2048, C=1024, H=16, D=64, F=4096, M=B*N=4096
// Pipeline:
//   ln1 -> q/k/v GEMMs -> RoPE(q,k) -> flash attention -> Wo GEMM (+x resid)
//   -> ln2 -> W1 GEMM (+GELU) -> W2 GEMM (+resid) -> d_out
// ---------------------------------------------------------------------------

#define Mrows 4096
#define Cdim  1024
#define Fdim  4096
#define Bb    2
#define Nn_   2048
#define Hh    16
#define Dd    64

#define OFF_H   ((size_t)0)
#define OFF_Q   ((size_t)4194304)
#define OFF_K   ((size_t)8388608)
#define OFF_V   ((size_t)12582912)
#define OFF_ATT ((size_t)16777216)
#define OFF_X2  ((size_t)20971520)
#define OFF_MLP ((size_t)25165824)
// total = 25165824 + 16777216 = 41943040 floats = 160 MB
__device__ float g_scratch[41943040];

// ---------------------------------------------------------------------------
// LayerNorm: one block (256 thr) per row of 1024
// ---------------------------------------------------------------------------
__global__ void __launch_bounds__(256) ln_kernel(
    const float* __restrict__ x, const float* __restrict__ g,
    const float* __restrict__ b, float* __restrict__ out)
{
    __shared__ float red[16];
    const int row = blockIdx.x;
    const int t = threadIdx.x;
    const float4 xv = ((const float4*)(x + (size_t)row * Cdim))[t];
    float s  = xv.x + xv.y + xv.z + xv.w;
    float ss = xv.x*xv.x + xv.y*xv.y + xv.z*xv.z + xv.w*xv.w;
    #pragma unroll
    for (int o = 16; o > 0; o >>= 1) {
        s  += __shfl_xor_sync(0xffffffffu, s,  o);
        ss += __shfl_xor_sync(0xffffffffu, ss, o);
    }
    const int w = t >> 5;
    if ((t & 31) == 0) { red[w] = s; red[8 + w] = ss; }
    __syncthreads();
    float ts = 0.f, tss = 0.f;
    #pragma unroll
    for (int i = 0; i < 8; i++) { ts += red[i]; tss += red[8 + i]; }
    const float mean = ts * (1.0f / Cdim);
    const float var  = tss * (1.0f / Cdim) - mean * mean;
    const float inv  = rsqrtf(var + 1e-6f);
    const float4 gv = ((const float4*)g)[t];
    const float4 bv = ((const float4*)b)[t];
    float4 o;
    o.x = (xv.x - mean) * inv * gv.x + bv.x;
    o.y = (xv.y - mean) * inv * gv.y + bv.y;
    o.z = (xv.z - mean) * inv * gv.z + bv.z;
    o.w = (xv.w - mean) * inv * gv.w + bv.w;
    ((float4*)(out + (size_t)row * Cdim))[t] = o;
}

// ---------------------------------------------------------------------------
// SGEMM: out[M,Nc] = A[M,K] @ W[Nc,K]^T + bias, optional GELU, optional resid
// 128x128 block tile, BK=16, 256 threads, 8x8 microtile.
// ---------------------------------------------------------------------------
__global__ void __launch_bounds__(256) sgemm_kernel(
    const float* __restrict__ A, const float* __restrict__ W,
    const float* __restrict__ bias, const float* __restrict__ residual,
    float* __restrict__ out, int M, int Nc, int K, int gelu)
{
    __shared__ float As[16][132];
    __shared__ float Bs[16][132];
    const int tid = threadIdx.x;
    const int tx = tid & 15, ty = tid >> 4;
    const int bm = blockIdx.y * 128, bn = blockIdx.x * 128;
    const int lrow = tid >> 1;
    const int lk = (tid & 1) * 4;
    const float* Ap = A + (size_t)(bm + lrow) * K + lk;
    const float* Wp = W + (size_t)(bn + lrow) * K + lk;

    float acc[8][8];
    #pragma unroll
    for (int i = 0; i < 8; i++)
        #pragma unroll
        for (int j = 0; j < 8; j++) acc[i][j] = 0.f;

    for (int k0 = 0; k0 < K; k0 += 16) {
        float4 a0 = *(const float4*)(Ap + k0);
        float4 a1 = *(const float4*)(Ap + k0 + 8);
        float4 w0 = *(const float4*)(Wp + k0);
        float4 w1 = *(const float4*)(Wp + k0 + 8);
        As[lk + 0][lrow] = a0.x; As[lk + 1][lrow] = a0.y;
        As[lk + 2][lrow] = a0.z; As[lk + 3][lrow] = a0.w;
        As[lk + 8][lrow] = a1.x; As[lk + 9][lrow] = a1.y;
        As[lk +10][lrow] = a1.z; As[lk +11][lrow] = a1.w;
        Bs[lk + 0][lrow] = w0.x; Bs[lk + 1][lrow] = w0.y;
        Bs[lk + 2][lrow] = w0.z; Bs[lk + 3][lrow] = w0.w;
        Bs[lk + 8][lrow] = w1.x; Bs[lk + 9][lrow] = w1.y;
        Bs[lk +10][lrow] = w1.z; Bs[lk +11][lrow] = w1.w;
        __syncthreads();
        #pragma unroll
        for (int k = 0; k < 16; k++) {
            float4 av0 = *(const float4*)&As[k][ty * 8];
            float4 av1 = *(const float4*)&As[k][ty * 8 + 4];
            float4 bv0 = *(const float4*)&Bs[k][tx * 8];
            float4 bv1 = *(const float4*)&Bs[k][tx * 8 + 4];
            const float a[8] = {av0.x, av0.y, av0.z, av0.w, av1.x, av1.y, av1.z, av1.w};
            const float bbv[8] = {bv0.x, bv0.y, bv0.z, bv0.w, bv1.x, bv1.y, bv1.z, bv1.w};
            #pragma unroll
            for (int i = 0; i < 8; i++)
                #pragma unroll
                for (int j = 0; j < 8; j++)
                    acc[i][j] = fmaf(a[i], bbv[j], acc[i][j]);
        }
        __syncthreads();
    }

    #pragma unroll
    for (int i = 0; i < 8; i++) {
        const int row = bm + ty * 8 + i;
        #pragma unroll
        for (int j = 0; j < 8; j++) {
            const int col = bn + tx * 8 + j;
            float val = acc[i][j] + __ldg(&bias[col]);
            if (gelu) val = 0.5f * val * (1.0f + erff(val * 0.70710678118654752f));
            if (residual) val += residual[(size_t)row * Nc + col];
            out[(size_t)row * Nc + col] = val;
        }
    }
}

// ---------------------------------------------------------------------------
// RoPE applied in place to q or k laid out as [B*N, C] with col = h*64 + d
// ---------------------------------------------------------------------------
__global__ void __launch_bounds__(256) rope_kernel(
    float* __restrict__ t, const float* __restrict__ cosb,
    const float* __restrict__ sinb)
{
    int idx = blockIdx.x * 256 + threadIdx.x;   // over B*N*H*32
    const int d = idx & 31; idx >>= 5;
    const int h = idx & (Hh - 1); idx >>= 4;
    const int n = idx & (Nn_ - 1); idx >>= 11;
    const int b = idx;
    const size_t base = ((size_t)(b * Nn_ + n)) * Cdim + h * Dd;
    const float x1 = t[base + d];
    const float x2 = t[base + d + 32];
    const float c1 = cosb[n * Dd + d],      s1 = sinb[n * Dd + d];
    const float c2 = cosb[n * Dd + d + 32], s2 = sinb[n * Dd + d + 32];
    t[base + d]      = x1 * c1 - x2 * s1;
    t[base + d + 32] = x2 * c2 + x1 * s2;
}

// ---------------------------------------------------------------------------
// Flash attention, fp32. Query tile 128, key tile 64, D=64.
// 256 threads = 16x16 grid; S microtile 8x4; row reductions via 16-lane shfl.
// q/k/v stay in [B*N, C] layout (row stride C, head slice of 64 contiguous).
// ---------------------------------------------------------------------------
#define QS_STRIDE 65
#define VS_STRIDE 68
#define FLASH_SMEM ((128*65 + 64*65 + 64*68 + 128*65) * 4)

__global__ void __launch_bounds__(256) flash_kernel(
    const float* __restrict__ q, const float* __restrict__ k,
    const float* __restrict__ v, float* __restrict__ out)
{
    extern __shared__ float sm[];
    float* Qs = sm;                        // [128][65]
    float* Ks = Qs + 128 * QS_STRIDE;      // [64][65]
    float* Vs = Ks + 64 * QS_STRIDE;       // [64][68]
    float* Ps = Vs + 64 * VS_STRIDE;       // [128][65]

    const int tid = threadIdx.x;
    const int tx = tid & 15, ty = tid >> 4;
    const int bh = blockIdx.y;
    const int b = bh >> 4;                 // H = 16
    const int h = bh & 15;
    const int q0 = blockIdx.x * 128;
    const float scale = 0.125f;            // D^-0.5

    const float* qb = q + ((size_t)(b * Nn_ + q0)) * Cdim + h * Dd;
    #pragma unroll
    for (int i = 0; i < 8; i++) {
        const int idx = tid + i * 256;     // float4 index 0..2047
        const int r = idx >> 4;
        const int c = (idx & 15) << 2;
        const float4 t4 = *(const float4*)(qb + (size_t)r * Cdim + c);
        float* dst = &Qs[r * QS_STRIDE + c];
        dst[0] = t4.x * scale; dst[1] = t4.y * scale;
        dst[2] = t4.z * scale; dst[3] = t4.w * scale;
    }

    float m_i[8], l_i[8], acc[8][4];
    #pragma unroll
    for (int i = 0; i < 8; i++) {
        m_i[i] = -1e30f; l_i[i] = 0.f;
        #pragma unroll
        for (int j = 0; j < 4; j++) acc[i][j] = 0.f;
    }

    for (int kv0 = 0; kv0 < Nn_; kv0 += 64) {
        __syncthreads();   // prior iter's Ks/Vs/Ps reads done (also orders Qs fill)
        const float* kb = k + ((size_t)(b * Nn_ + kv0)) * Cdim + h * Dd;
        const float* vb = v + ((size_t)(b * Nn_ + kv0)) * Cdim + h * Dd;
        #pragma unroll
        for (int i = 0; i < 4; i++) {
            const int idx = tid + i * 256; // float4 index 0..1023
            const int r = idx >> 4;
            const int c = (idx & 15) << 2;
            const float4 kt = *(const float4*)(kb + (size_t)r * Cdim + c);
            const float4 vt = *(const float4*)(vb + (size_t)r * Cdim + c);
            float* kd = &Ks[r * QS_STRIDE + c];
            kd[0] = kt.x; kd[1] = kt.y; kd[2] = kt.z; kd[3] = kt.w;
            float* vd = &Vs[r * VS_STRIDE + c];
            vd[0] = vt.x; vd[1] = vt.y; vd[2] = vt.z; vd[3] = vt.w;
        }
        __syncthreads();

        // S = (Q*scale) @ K^T   [128 x 64], microtile 8x4
        float s[8][4];
        #pragma unroll
        for (int i = 0; i < 8; i++)
            #pragma unroll
            for (int j = 0; j < 4; j++) s[i][j] = 0.f;
        #pragma unroll 8
        for (int d = 0; d < 64; d++) {
            float a[8], bb[4];
            #pragma unroll
            for (int i = 0; i < 8; i++) a[i] = Qs[(ty * 8 + i) * QS_STRIDE + d];
            #pragma unroll
            for (int j = 0; j < 4; j++) bb[j] = Ks[(tx * 4 + j) * QS_STRIDE + d];
            #pragma unroll
            for (int i = 0; i < 8; i++)
                #pragma unroll
                for (int j = 0; j < 4; j++)
                    s[i][j] = fmaf(a[i], bb[j], s[i][j]);
        }

        // online softmax per row (row group = 16 lanes sharing ty)
        #pragma unroll
        for (int i = 0; i < 8; i++) {
            float mx = fmaxf(fmaxf(s[i][0], s[i][1]), fmaxf(s[i][2], s[i][3]));
            #pragma unroll
            for (int o = 8; o > 0; o >>= 1)
                mx = fmaxf(mx, __shfl_xor_sync(0xffffffffu, mx, o, 16));
            const float mnew = fmaxf(m_i[i], mx);
            const float alpha = __expf(m_i[i] - mnew);
            float rs = 0.f;
            #pragma unroll
            for (int j = 0; j < 4; j++) {
                const float p = __expf(s[i][j] - mnew);
                rs += p;
                Ps[(ty * 8 + i) * QS_STRIDE + tx * 4 + j] = p;
            }
            #pragma unroll
            for (int o = 8; o > 0; o >>= 1)
                rs += __shfl_xor_sync(0xffffffffu, rs, o, 16);
            l_i[i] = l_i[i] * alpha + rs;
            m_i[i] = mnew;
            #pragma unroll
            for (int j = 0; j < 4; j++) acc[i][j] *= alpha;
        }
        __syncthreads();

        // O += P @ V   [128 x 64]
        #pragma unroll 8
        for (int c = 0; c < 64; c++) {
            float a[8], bb[4];
            #pragma unroll
            for (int i = 0; i < 8; i++) a[i] = Ps[(ty * 8 + i) * QS_STRIDE + c];
            #pragma unroll
            for (int j = 0; j < 4; j++) bb[j] = Vs[c * VS_STRIDE + tx * 4 + j];
            #pragma unroll
            for (int i = 0; i < 8; i++)
                #pragma unroll
                for (int j = 0; j < 4; j++)
                    acc[i][j] = fmaf(a[i], bb[j], acc[i][j]);
        }
    }

    float* ob = out + ((size_t)(b * Nn_ + q0)) * Cdim + h * Dd;
    #pragma unroll
    for (int i = 0; i < 8; i++) {
        const float invl = 1.0f / l_i[i];
        float4 o;
        o.x = acc[i][0] * invl; o.y = acc[i][1] * invl;
        o.z = acc[i][2] * invl; o.w = acc[i][3] * invl;
        *(float4*)(ob + (size_t)(ty * 8 + i) * Cdim + tx * 4) = o;
    }
}

// ---------------------------------------------------------------------------
extern "C" void kernel_launch(void* const* d_in, const int* in_sizes, int n_in,
                              void* d_out, int out_size)
{
    const float* x    = (const float*)d_in[0];
    const float* rcos = (const float*)d_in[1];
    const float* rsin = (const float*)d_in[2];
    const float* g1   = (const float*)d_in[3];
    const float* be1  = (const float*)d_in[4];
    const float* Wq   = (const float*)d_in[5];
    const float* bq   = (const float*)d_in[6];
    const float* Wk   = (const float*)d_in[7];
    const float* bk   = (const float*)d_in[8];
    const float* Wv   = (const float*)d_in[9];
    const float* bv   = (const float*)d_in[10];
    const float* Wo   = (const float*)d_in[11];
    const float* bo   = (const float*)d_in[12];
    const float* g2   = (const float*)d_in[13];
    const float* be2  = (const float*)d_in[14];
    const float* W1   = (const float*)d_in[15];
    const float* b1   = (const float*)d_in[16];
    const float* W2   = (const float*)d_in[17];
    const float* b2   = (const float*)d_in[18];
    float* out = (float*)d_out;

    float* base = nullptr;
    cudaGetSymbolAddress((void**)&base, g_scratch);
    float* p_h   = base + OFF_H;
    float* p_q   = base + OFF_Q;
    float* p_k   = base + OFF_K;
    float* p_v   = base + OFF_V;
    float* p_att = base + OFF_ATT;
    float* p_x2  = base + OFF_X2;
    float* p_mlp = base + OFF_MLP;

    cudaFuncSetAttribute(flash_kernel,
                         cudaFuncAttributeMaxDynamicSharedMemorySize, FLASH_SMEM);

    // 1. LN1
    ln_kernel<<<Mrows, 256>>>(x, g1, be1, p_h);

    // 2. QKV projections
    dim3 gC(Cdim / 128, Mrows / 128);       // (8, 32)
    sgemm_kernel<<<gC, 256>>>(p_h, Wq, bq, nullptr, p_q, Mrows, Cdim, Cdim, 0);
    sgemm_kernel<<<gC, 256>>>(p_h, Wk, bk, nullptr, p_k, Mrows, Cdim, Cdim, 0);
    sgemm_kernel<<<gC, 256>>>(p_h, Wv, bv, nullptr, p_v, Mrows, Cdim, Cdim, 0);

    // 3. RoPE on q and k
    const int rblocks = (Bb * Nn_ * Hh * 32) / 256;  // 8192
    rope_kernel<<<rblocks, 256>>>(p_q, rcos, rsin);
    rope_kernel<<<rblocks, 256>>>(p_k, rcos, rsin);

    // 4. attention
    flash_kernel<<<dim3(Nn_ / 128, Bb * Hh), 256, FLASH_SMEM>>>(p_q, p_k, p_v, p_att);

    // 5. output projection + residual with x
    sgemm_kernel<<<gC, 256>>>(p_att, Wo, bo, x, p_x2, Mrows, Cdim, Cdim, 0);

    // 6. LN2
    ln_kernel<<<Mrows, 256>>>(p_x2, g2, be2, p_h);

    // 7. MLP up + GELU
    dim3 gF(Fdim / 128, Mrows / 128);       // (32, 32)
    sgemm_kernel<<<gF, 256>>>(p_h, W1, b1, nullptr, p_mlp, Mrows, Fdim, Cdim, 1);

    // 8. MLP down + residual -> output
    sgemm_kernel<<<gC, 256>>>(p_mlp, W2, b2, p_x2, out, Mrows, Cdim, Fdim, 0);
}

// round 3
// speedup vs baseline: 1.8344x; 1.8344x over previous
#include <cuda_runtime.h>
#include <cuda_bf16.h>
#include <stdint.h>
#include <math.h>

// ---------------------------------------------------------------------------
// DiT block. Round 3: all GEMMs on tensor cores via mma.sync tf32.
//   B=2, N=2048, C=1024, H=16, D=64, F=4096, M=B*N=4096
// ---------------------------------------------------------------------------

#define Mrows 4096
#define Cdim  1024
#define Fdim  4096
#define Bb    2
#define Nn_   2048
#define Hh    16
#define Dd    64

#define OFF_H   ((size_t)0)
#define OFF_Q   ((size_t)4194304)
#define OFF_K   ((size_t)8388608)
#define OFF_V   ((size_t)12582912)
#define OFF_ATT ((size_t)16777216)
#define OFF_X2  ((size_t)20971520)
#define OFF_MLP ((size_t)25165824)
__device__ float g_scratch[41943040];

__device__ __forceinline__ uint32_t f2tf32(float x) {
    uint32_t t;
    asm("cvt.rna.tf32.f32 %0, %1;" : "=r"(t) : "f"(x));
    return t;
}

#define MMA_TF32(d, a, b)                                                     \
    asm volatile(                                                             \
        "mma.sync.aligned.m16n8k8.row.col.f32.tf32.tf32.f32 "                 \
        "{%0,%1,%2,%3}, {%4,%5,%6,%7}, {%8,%9}, {%0,%1,%2,%3};"               \
        : "+f"(d[0]), "+f"(d[1]), "+f"(d[2]), "+f"(d[3])                      \
        : "r"(a[0]), "r"(a[1]), "r"(a[2]), "r"(a[3]), "r"(b[0]), "r"(b[1]))

// ---------------------------------------------------------------------------
// LayerNorm: one block (256 thr) per row of 1024
// ---------------------------------------------------------------------------
__global__ void __launch_bounds__(256) ln_kernel(
    const float* __restrict__ x, const float* __restrict__ g,
    const float* __restrict__ b, float* __restrict__ out)
{
    __shared__ float red[16];
    const int row = blockIdx.x;
    const int t = threadIdx.x;
    const float4 xv = ((const float4*)(x + (size_t)row * Cdim))[t];
    float s  = xv.x + xv.y + xv.z + xv.w;
    float ss = xv.x*xv.x + xv.y*xv.y + xv.z*xv.z + xv.w*xv.w;
    #pragma unroll
    for (int o = 16; o > 0; o >>= 1) {
        s  += __shfl_xor_sync(0xffffffffu, s,  o);
        ss += __shfl_xor_sync(0xffffffffu, ss, o);
    }
    const int w = t >> 5;
    if ((t & 31) == 0) { red[w] = s; red[8 + w] = ss; }
    __syncthreads();
    float ts = 0.f, tss = 0.f;
    #pragma unroll
    for (int i = 0; i < 8; i++) { ts += red[i]; tss += red[8 + i]; }
    const float mean = ts * (1.0f / Cdim);
    const float var  = tss * (1.0f / Cdim) - mean * mean;
    const float inv  = rsqrtf(var + 1e-6f);
    const float4 gv = ((const float4*)g)[t];
    const float4 bv = ((const float4*)b)[t];
    float4 o;
    o.x = (xv.x - mean) * inv * gv.x + bv.x;
    o.y = (xv.y - mean) * inv * gv.y + bv.y;
    o.z = (xv.z - mean) * inv * gv.z + bv.z;
    o.w = (xv.w - mean) * inv * gv.w + bv.w;
    ((float4*)(out + (size_t)row * Cdim))[t] = o;
}

// ---------------------------------------------------------------------------
// tf32 tensor-core GEMM: out[M,Nc] = A[M,K] @ W[Nc,K]^T + bias (+GELU)(+resid)
// 128x128 block tile, BK=32, 256 threads (8 warps, 2x4), warp tile 64x32.
// ---------------------------------------------------------------------------
#define BKq 32
#define SPAD 34

__global__ void __launch_bounds__(256, 2) tgemm_kernel(
    const float* __restrict__ A, const float* __restrict__ W,
    const float* __restrict__ bias, const float* __restrict__ residual,
    float* __restrict__ out, int M, int Nc, int K, int gelu)
{
    __shared__ uint32_t As[128][SPAD];
    __shared__ uint32_t Bs[128][SPAD];

    const int tid  = threadIdx.x;
    const int wid  = tid >> 5;
    const int lane = tid & 31;
    const int lr   = lane >> 2;   // 0..7
    const int lc   = lane & 3;    // 0..3
    const int warpM = (wid & 1) * 64;
    const int warpN = (wid >> 1) * 32;
    const int bm = blockIdx.y * 128, bn = blockIdx.x * 128;

    float acc[4][4][4];
    #pragma unroll
    for (int i = 0; i < 4; i++)
        #pragma unroll
        for (int j = 0; j < 4; j++)
            #pragma unroll
            for (int r = 0; r < 4; r++) acc[i][j][r] = 0.f;

    const int lrow = tid >> 3;          // 0..31
    const int lcol = (tid & 7) << 2;    // 0,4,...,28

    for (int k0 = 0; k0 < K; k0 += BKq) {
        #pragma unroll
        for (int p = 0; p < 4; p++) {
            const int row = lrow + p * 32;
            const float4 av = *(const float4*)(A + (size_t)(bm + row) * K + k0 + lcol);
            const float4 wv = *(const float4*)(W + (size_t)(bn + row) * K + k0 + lcol);
            As[row][lcol + 0] = f2tf32(av.x);
            As[row][lcol + 1] = f2tf32(av.y);
            As[row][lcol + 2] = f2tf32(av.z);
            As[row][lcol + 3] = f2tf32(av.w);
            Bs[row][lcol + 0] = f2tf32(wv.x);
            Bs[row][lcol + 1] = f2tf32(wv.y);
            Bs[row][lcol + 2] = f2tf32(wv.z);
            Bs[row][lcol + 3] = f2tf32(wv.w);
        }
        __syncthreads();

        #pragma unroll
        for (int ks = 0; ks < 4; ks++) {
            const int kk = ks * 8;
            uint32_t af[4][4], bf[4][2];
            #pragma unroll
            for (int i = 0; i < 4; i++) {
                const int rb = warpM + i * 16;
                af[i][0] = As[rb + lr][kk + lc];
                af[i][1] = As[rb + lr + 8][kk + lc];
                af[i][2] = As[rb + lr][kk + lc + 4];
                af[i][3] = As[rb + lr + 8][kk + lc + 4];
            }
            #pragma unroll
            for (int j = 0; j < 4; j++) {
                const int cb = warpN + j * 8;
                bf[j][0] = Bs[cb + lr][kk + lc];
                bf[j][1] = Bs[cb + lr][kk + lc + 4];
            }
            #pragma unroll
            for (int i = 0; i < 4; i++)
                #pragma unroll
                for (int j = 0; j < 4; j++)
                    MMA_TF32(acc[i][j], af[i], bf[j]);
        }
        __syncthreads();
    }

    // epilogue
    #pragma unroll
    for (int i = 0; i < 4; i++) {
        const int row0 = bm + warpM + i * 16 + lr;
        #pragma unroll
        for (int j = 0; j < 4; j++) {
            const int col = bn + warpN + j * 8 + (lc << 1);
            const float b0 = __ldg(&bias[col]);
            const float b1 = __ldg(&bias[col + 1]);
            float v0 = acc[i][j][0] + b0;
            float v1 = acc[i][j][1] + b1;
            float v2 = acc[i][j][2] + b0;
            float v3 = acc[i][j][3] + b1;
            if (gelu) {
                v0 = 0.5f * v0 * (1.0f + erff(v0 * 0.70710678118654752f));
                v1 = 0.5f * v1 * (1.0f + erff(v1 * 0.70710678118654752f));
                v2 = 0.5f * v2 * (1.0f + erff(v2 * 0.70710678118654752f));
                v3 = 0.5f * v3 * (1.0f + erff(v3 * 0.70710678118654752f));
            }
            if (residual) {
                v0 += residual[(size_t)row0 * Nc + col];
                v1 += residual[(size_t)row0 * Nc + col + 1];
                v2 += residual[(size_t)(row0 + 8) * Nc + col];
                v3 += residual[(size_t)(row0 + 8) * Nc + col + 1];
            }
            *(float2*)(out + (size_t)row0 * Nc + col)       = make_float2(v0, v1);
            *(float2*)(out + (size_t)(row0 + 8) * Nc + col) = make_float2(v2, v3);
        }
    }
}

// ---------------------------------------------------------------------------
// RoPE applied in place to q or k laid out as [B*N, C] with col = h*64 + d
// ---------------------------------------------------------------------------
__global__ void __launch_bounds__(256) rope_kernel(
    float* __restrict__ t, const float* __restrict__ cosb,
    const float* __restrict__ sinb)
{
    int idx = blockIdx.x * 256 + threadIdx.x;
    const int d = idx & 31; idx >>= 5;
    const int h = idx & (Hh - 1); idx >>= 4;
    const int n = idx & (Nn_ - 1); idx >>= 11;
    const int b = idx;
    const size_t base = ((size_t)(b * Nn_ + n)) * Cdim + h * Dd;
    const float x1 = t[base + d];
    const float x2 = t[base + d + 32];
    const float c1 = cosb[n * Dd + d],      s1 = sinb[n * Dd + d];
    const float c2 = cosb[n * Dd + d + 32], s2 = sinb[n * Dd + d + 32];
    t[base + d]      = x1 * c1 - x2 * s1;
    t[base + d + 32] = x2 * c2 + x1 * s2;
}

// ---------------------------------------------------------------------------
// Flash attention, fp32 SIMT (unchanged from R1).
// ---------------------------------------------------------------------------
#define QS_STRIDE 65
#define VS_STRIDE 68
#define FLASH_SMEM ((128*65 + 64*65 + 64*68 + 128*65) * 4)

__global__ void __launch_bounds__(256) flash_kernel(
    const float* __restrict__ q, const float* __restrict__ k,
    const float* __restrict__ v, float* __restrict__ out)
{
    extern __shared__ float sm[];
    float* Qs = sm;
    float* Ks = Qs + 128 * QS_STRIDE;
    float* Vs = Ks + 64 * QS_STRIDE;
    float* Ps = Vs + 64 * VS_STRIDE;

    const int tid = threadIdx.x;
    const int tx = tid & 15, ty = tid >> 4;
    const int bh = blockIdx.y;
    const int b = bh >> 4;
    const int h = bh & 15;
    const int q0 = blockIdx.x * 128;
    const float scale = 0.125f;

    const float* qb = q + ((size_t)(b * Nn_ + q0)) * Cdim + h * Dd;
    #pragma unroll
    for (int i = 0; i < 8; i++) {
        const int idx = tid + i * 256;
        const int r = idx >> 4;
        const int c = (idx & 15) << 2;
        const float4 t4 = *(const float4*)(qb + (size_t)r * Cdim + c);
        float* dst = &Qs[r * QS_STRIDE + c];
        dst[0] = t4.x * scale; dst[1] = t4.y * scale;
        dst[2] = t4.z * scale; dst[3] = t4.w * scale;
    }

    float m_i[8], l_i[8], acc[8][4];
    #pragma unroll
    for (int i = 0; i < 8; i++) {
        m_i[i] = -1e30f; l_i[i] = 0.f;
        #pragma unroll
        for (int j = 0; j < 4; j++) acc[i][j] = 0.f;
    }

    for (int kv0 = 0; kv0 < Nn_; kv0 += 64) {
        __syncthreads();
        const float* kb = k + ((size_t)(b * Nn_ + kv0)) * Cdim + h * Dd;
        const float* vb = v + ((size_t)(b * Nn_ + kv0)) * Cdim + h * Dd;
        #pragma unroll
        for (int i = 0; i < 4; i++) {
            const int idx = tid + i * 256;
            const int r = idx >> 4;
            const int c = (idx & 15) << 2;
            const float4 kt = *(const float4*)(kb + (size_t)r * Cdim + c);
            const float4 vt = *(const float4*)(vb + (size_t)r * Cdim + c);
            float* kd = &Ks[r * QS_STRIDE + c];
            kd[0] = kt.x; kd[1] = kt.y; kd[2] = kt.z; kd[3] = kt.w;
            float* vd = &Vs[r * VS_STRIDE + c];
            vd[0] = vt.x; vd[1] = vt.y; vd[2] = vt.z; vd[3] = vt.w;
        }
        __syncthreads();

        float s[8][4];
        #pragma unroll
        for (int i = 0; i < 8; i++)
            #pragma unroll
            for (int j = 0; j < 4; j++) s[i][j] = 0.f;
        #pragma unroll 8
        for (int d = 0; d < 64; d++) {
            float a[8], bb[4];
            #pragma unroll
            for (int i = 0; i < 8; i++) a[i] = Qs[(ty * 8 + i) * QS_STRIDE + d];
            #pragma unroll
            for (int j = 0; j < 4; j++) bb[j] = Ks[(tx * 4 + j) * QS_STRIDE + d];
            #pragma unroll
            for (int i = 0; i < 8; i++)
                #pragma unroll
                for (int j = 0; j < 4; j++)
                    s[i][j] = fmaf(a[i], bb[j], s[i][j]);
        }

        #pragma unroll
        for (int i = 0; i < 8; i++) {
            float mx = fmaxf(fmaxf(s[i][0], s[i][1]), fmaxf(s[i][2], s[i][3]));
            #pragma unroll
            for (int o = 8; o > 0; o >>= 1)
                mx = fmaxf(mx, __shfl_xor_sync(0xffffffffu, mx, o, 16));
            const float mnew = fmaxf(m_i[i], mx);
            const float alpha = __expf(m_i[i] - mnew);
            float rs = 0.f;
            #pragma unroll
            for (int j = 0; j < 4; j++) {
                const float p = __expf(s[i][j] - mnew);
                rs += p;
                Ps[(ty * 8 + i) * QS_STRIDE + tx * 4 + j] = p;
            }
            #pragma unroll
            for (int o = 8; o > 0; o >>= 1)
                rs += __shfl_xor_sync(0xffffffffu, rs, o, 16);
            l_i[i] = l_i[i] * alpha + rs;
            m_i[i] = mnew;
            #pragma unroll
            for (int j = 0; j < 4; j++) acc[i][j] *= alpha;
        }
        __syncthreads();

        #pragma unroll 8
        for (int c = 0; c < 64; c++) {
            float a[8], bb[4];
            #pragma unroll
            for (int i = 0; i < 8; i++) a[i] = Ps[(ty * 8 + i) * QS_STRIDE + c];
            #pragma unroll
            for (int j = 0; j < 4; j++) bb[j] = Vs[c * VS_STRIDE + tx * 4 + j];
            #pragma unroll
            for (int i = 0; i < 8; i++)
                #pragma unroll
                for (int j = 0; j < 4; j++)
                    acc[i][j] = fmaf(a[i], bb[j], acc[i][j]);
        }
    }

    float* ob = out + ((size_t)(b * Nn_ + q0)) * Cdim + h * Dd;
    #pragma unroll
    for (int i = 0; i < 8; i++) {
        const float invl = 1.0f / l_i[i];
        float4 o;
        o.x = acc[i][0] * invl; o.y = acc[i][1] * invl;
        o.z = acc[i][2] * invl; o.w = acc[i][3] * invl;
        *(float4*)(ob + (size_t)(ty * 8 + i) * Cdim + tx * 4) = o;
    }
}

// ---------------------------------------------------------------------------
extern "C" void kernel_launch(void* const* d_in, const int* in_sizes, int n_in,
                              void* d_out, int out_size)
{
    const float* x    = (const float*)d_in[0];
    const float* rcos = (const float*)d_in[1];
    const float* rsin = (const float*)d_in[2];
    const float* g1   = (const float*)d_in[3];
    const float* be1  = (const float*)d_in[4];
    const float* Wq   = (const float*)d_in[5];
    const float* bq   = (const float*)d_in[6];
    const float* Wk   = (const float*)d_in[7];
    const float* bk   = (const float*)d_in[8];
    const float* Wv   = (const float*)d_in[9];
    const float* bv   = (const float*)d_in[10];
    const float* Wo   = (const float*)d_in[11];
    const float* bo   = (const float*)d_in[12];
    const float* g2   = (const float*)d_in[13];
    const float* be2  = (const float*)d_in[14];
    const float* W1   = (const float*)d_in[15];
    const float* b1   = (const float*)d_in[16];
    const float* W2   = (const float*)d_in[17];
    const float* b2   = (const float*)d_in[18];
    float* out = (float*)d_out;

    float* base = nullptr;
    cudaGetSymbolAddress((void**)&base, g_scratch);
    float* p_h   = base + OFF_H;
    float* p_q   = base + OFF_Q;
    float* p_k   = base + OFF_K;
    float* p_v   = base + OFF_V;
    float* p_att = base + OFF_ATT;
    float* p_x2  = base + OFF_X2;
    float* p_mlp = base + OFF_MLP;

    cudaFuncSetAttribute(flash_kernel,
                         cudaFuncAttributeMaxDynamicSharedMemorySize, FLASH_SMEM);

    // 1. LN1
    ln_kernel<<<Mrows, 256>>>(x, g1, be1, p_h);

    // 2. QKV projections (tensor cores)
    dim3 gC(Cdim / 128, Mrows / 128);
    tgemm_kernel<<<gC, 256>>>(p_h, Wq, bq, nullptr, p_q, Mrows, Cdim, Cdim, 0);
    tgemm_kernel<<<gC, 256>>>(p_h, Wk, bk, nullptr, p_k, Mrows, Cdim, Cdim, 0);
    tgemm_kernel<<<gC, 256>>>(p_h, Wv, bv, nullptr, p_v, Mrows, Cdim, Cdim, 0);

    // 3. RoPE
    const int rblocks = (Bb * Nn_ * Hh * 32) / 256;
    rope_kernel<<<rblocks, 256>>>(p_q, rcos, rsin);
    rope_kernel<<<rblocks, 256>>>(p_k, rcos, rsin);

    // 4. attention
    flash_kernel<<<dim3(Nn_ / 128, Bb * Hh), 256, FLASH_SMEM>>>(p_q, p_k, p_v, p_att);

    // 5. output projection + residual
    tgemm_kernel<<<gC, 256>>>(p_att, Wo, bo, x, p_x2, Mrows, Cdim, Cdim, 0);

    // 6. LN2
    ln_kernel<<<Mrows, 256>>>(p_x2, g2, be2, p_h);

    // 7. MLP up + GELU
    dim3 gF(Fdim / 128, Mrows / 128);
    tgemm_kernel<<<gF, 256>>>(p_h, W1, b1, nullptr, p_mlp, Mrows, Fdim, Cdim, 1);

    // 8. MLP down + residual -> output
    tgemm_kernel<<<gC, 256>>>(p_mlp, W2, b2, p_x2, out, Mrows, Cdim, Fdim, 0);
}

// round 4
// speedup vs baseline: 3.4284x; 1.8689x over previous
#include <cuda_runtime.h>
#include <cuda_bf16.h>
#include <stdint.h>
#include <math.h>

// ---------------------------------------------------------------------------
// DiT block. Round 4: tf32 tensor cores everywhere (GEMMs + flash attention),
// cp.async double-buffered GEMM, raw-fp32 (truncated) tf32 operands.
//   B=2, N=2048, C=1024, H=16, D=64, F=4096, M=B*N=4096
// ---------------------------------------------------------------------------

#define Mrows 4096
#define Cdim  1024
#define Fdim  4096
#define Bb    2
#define Nn_   2048
#define Hh    16
#define Dd    64

#define OFF_H   ((size_t)0)
#define OFF_Q   ((size_t)4194304)
#define OFF_K   ((size_t)8388608)
#define OFF_V   ((size_t)12582912)
#define OFF_ATT ((size_t)16777216)
#define OFF_X2  ((size_t)20971520)
#define OFF_MLP ((size_t)25165824)
__device__ float g_scratch[41943040];

#define MMA_TF32(d, a, b)                                                     \
    asm volatile(                                                             \
        "mma.sync.aligned.m16n8k8.row.col.f32.tf32.tf32.f32 "                 \
        "{%0,%1,%2,%3}, {%4,%5,%6,%7}, {%8,%9}, {%0,%1,%2,%3};"               \
        : "+f"(d[0]), "+f"(d[1]), "+f"(d[2]), "+f"(d[3])                      \
        : "r"(a[0]), "r"(a[1]), "r"(a[2]), "r"(a[3]), "r"(b[0]), "r"(b[1]))

#define CP_ASYNC16(dst_u32, src_ptr)                                          \
    asm volatile("cp.async.cg.shared.global [%0], [%1], 16;"                  \
                 :: "r"(dst_u32), "l"(src_ptr))
#define CP_COMMIT()  asm volatile("cp.async.commit_group;")
#define CP_WAIT(n)   asm volatile("cp.async.wait_group %0;" :: "n"(n))

// ---------------------------------------------------------------------------
// LayerNorm: one block (256 thr) per row of 1024
// ---------------------------------------------------------------------------
__global__ void __launch_bounds__(256) ln_kernel(
    const float* __restrict__ x, const float* __restrict__ g,
    const float* __restrict__ b, float* __restrict__ out)
{
    __shared__ float red[16];
    const int row = blockIdx.x;
    const int t = threadIdx.x;
    const float4 xv = ((const float4*)(x + (size_t)row * Cdim))[t];
    float s  = xv.x + xv.y + xv.z + xv.w;
    float ss = xv.x*xv.x + xv.y*xv.y + xv.z*xv.z + xv.w*xv.w;
    #pragma unroll
    for (int o = 16; o > 0; o >>= 1) {
        s  += __shfl_xor_sync(0xffffffffu, s,  o);
        ss += __shfl_xor_sync(0xffffffffu, ss, o);
    }
    const int w = t >> 5;
    if ((t & 31) == 0) { red[w] = s; red[8 + w] = ss; }
    __syncthreads();
    float ts = 0.f, tss = 0.f;
    #pragma unroll
    for (int i = 0; i < 8; i++) { ts += red[i]; tss += red[8 + i]; }
    const float mean = ts * (1.0f / Cdim);
    const float var  = tss * (1.0f / Cdim) - mean * mean;
    const float inv  = rsqrtf(var + 1e-6f);
    const float4 gv = ((const float4*)g)[t];
    const float4 bv = ((const float4*)b)[t];
    float4 o;
    o.x = (xv.x - mean) * inv * gv.x + bv.x;
    o.y = (xv.y - mean) * inv * gv.y + bv.y;
    o.z = (xv.z - mean) * inv * gv.z + bv.z;
    o.w = (xv.w - mean) * inv * gv.w + bv.w;
    ((float4*)(out + (size_t)row * Cdim))[t] = o;
}

// ---------------------------------------------------------------------------
// tf32 GEMM, cp.async double-buffered.
// out[M,Nc] = A[M,K] @ W[Nc,K]^T + bias (+GELU)(+resid)
// 128x128 tile, BK=32, 256 threads (8 warps 2x4), warp tile 64x32.
// Dynamic smem: As[2][128][36] + Bs[2][128][36] floats = 73728 B.
// ---------------------------------------------------------------------------
#define GS 36
#define GBUF (128 * GS)
#define GEMM_SMEM (2 * 2 * GBUF * 4)

__global__ void __launch_bounds__(256, 2) tgemm_kernel(
    const float* __restrict__ A, const float* __restrict__ W,
    const float* __restrict__ bias, const float* __restrict__ residual,
    float* __restrict__ out, int M, int Nc, int K, int gelu)
{
    extern __shared__ float smf[];
    float* As = smf;                 // [2][128][36]
    float* Bs = smf + 2 * GBUF;      // [2][128][36]
    const uint32_t sb = (uint32_t)__cvta_generic_to_shared(smf);

    const int tid  = threadIdx.x;
    const int wid  = tid >> 5;
    const int lane = tid & 31;
    const int lr   = lane >> 2;
    const int lc   = lane & 3;
    const int warpM = (wid & 1) * 64;
    const int warpN = (wid >> 1) * 32;
    const int bm = blockIdx.y * 128, bn = blockIdx.x * 128;

    const int lrow = tid >> 3;          // 0..31 (x4 = 128 rows)
    const int lcol = (tid & 7) << 2;    // 0,4,...,28

    float acc[4][4][4];
    #pragma unroll
    for (int i = 0; i < 4; i++)
        #pragma unroll
        for (int j = 0; j < 4; j++)
            #pragma unroll
            for (int r = 0; r < 4; r++) acc[i][j][r] = 0.f;

    const int nk = K >> 5;

    // async tile loader: stage 'buf', k offset k0
    #define LOAD_TILE(buf, k0)                                                \
    do {                                                                      \
        _Pragma("unroll")                                                     \
        for (int p = 0; p < 4; p++) {                                         \
            const int row = lrow + p * 32;                                    \
            const uint32_t da = sb + (uint32_t)(((buf) * GBUF + row * GS + lcol) * 4); \
            const uint32_t db = da + (uint32_t)(2 * GBUF * 4);                \
            CP_ASYNC16(da, A + (size_t)(bm + row) * K + (k0) + lcol);         \
            CP_ASYNC16(db, W + (size_t)(bn + row) * K + (k0) + lcol);         \
        }                                                                     \
    } while (0)

    LOAD_TILE(0, 0);
    CP_COMMIT();

    for (int kt = 0; kt < nk; kt++) {
        const int buf = kt & 1;
        if (kt + 1 < nk) {
            LOAD_TILE(buf ^ 1, (kt + 1) << 5);
            CP_COMMIT();
            CP_WAIT(1);
        } else {
            CP_WAIT(0);
        }
        __syncthreads();

        const float* Ab = As + buf * GBUF;
        const float* Bbf = Bs + buf * GBUF;
        #pragma unroll
        for (int ks = 0; ks < 4; ks++) {
            const int kk = ks * 8;
            uint32_t af[4][4], bf[4][2];
            #pragma unroll
            for (int i = 0; i < 4; i++) {
                const int rb = warpM + i * 16;
                af[i][0] = __float_as_uint(Ab[(rb + lr) * GS + kk + lc]);
                af[i][1] = __float_as_uint(Ab[(rb + lr + 8) * GS + kk + lc]);
                af[i][2] = __float_as_uint(Ab[(rb + lr) * GS + kk + lc + 4]);
                af[i][3] = __float_as_uint(Ab[(rb + lr + 8) * GS + kk + lc + 4]);
            }
            #pragma unroll
            for (int j = 0; j < 4; j++) {
                const int cb = warpN + j * 8;
                bf[j][0] = __float_as_uint(Bbf[(cb + lr) * GS + kk + lc]);
                bf[j][1] = __float_as_uint(Bbf[(cb + lr) * GS + kk + lc + 4]);
            }
            #pragma unroll
            for (int i = 0; i < 4; i++)
                #pragma unroll
                for (int j = 0; j < 4; j++)
                    MMA_TF32(acc[i][j], af[i], bf[j]);
        }
        __syncthreads();
    }

    // epilogue
    #pragma unroll
    for (int i = 0; i < 4; i++) {
        const int row0 = bm + warpM + i * 16 + lr;
        #pragma unroll
        for (int j = 0; j < 4; j++) {
            const int col = bn + warpN + j * 8 + (lc << 1);
            const float b0 = __ldg(&bias[col]);
            const float b1 = __ldg(&bias[col + 1]);
            float v0 = acc[i][j][0] + b0;
            float v1 = acc[i][j][1] + b1;
            float v2 = acc[i][j][2] + b0;
            float v3 = acc[i][j][3] + b1;
            if (gelu) {
                v0 = 0.5f * v0 * (1.0f + erff(v0 * 0.70710678118654752f));
                v1 = 0.5f * v1 * (1.0f + erff(v1 * 0.70710678118654752f));
                v2 = 0.5f * v2 * (1.0f + erff(v2 * 0.70710678118654752f));
                v3 = 0.5f * v3 * (1.0f + erff(v3 * 0.70710678118654752f));
            }
            if (residual) {
                v0 += residual[(size_t)row0 * Nc + col];
                v1 += residual[(size_t)row0 * Nc + col + 1];
                v2 += residual[(size_t)(row0 + 8) * Nc + col];
                v3 += residual[(size_t)(row0 + 8) * Nc + col + 1];
            }
            *(float2*)(out + (size_t)row0 * Nc + col)       = make_float2(v0, v1);
            *(float2*)(out + (size_t)(row0 + 8) * Nc + col) = make_float2(v2, v3);
        }
    }
}

// ---------------------------------------------------------------------------
// RoPE applied in place to q or k laid out as [B*N, C] with col = h*64 + d
// ---------------------------------------------------------------------------
__global__ void __launch_bounds__(256) rope_kernel(
    float* __restrict__ t, const float* __restrict__ cosb,
    const float* __restrict__ sinb)
{
    int idx = blockIdx.x * 256 + threadIdx.x;
    const int d = idx & 31; idx >>= 5;
    const int h = idx & (Hh - 1); idx >>= 4;
    const int n = idx & (Nn_ - 1); idx >>= 11;
    const int b = idx;
    const size_t base = ((size_t)(b * Nn_ + n)) * Cdim + h * Dd;
    const float x1 = t[base + d];
    const float x2 = t[base + d + 32];
    const float c1 = cosb[n * Dd + d],      s1 = sinb[n * Dd + d];
    const float c2 = cosb[n * Dd + d + 32], s2 = sinb[n * Dd + d + 32];
    t[base + d]      = x1 * c1 - x2 * s1;
    t[base + d + 32] = x2 * c2 + x1 * s2;
}

// ---------------------------------------------------------------------------
// Flash attention on tensor cores (tf32 mma, fp32 accumulate).
// Q tile 128 x D=64; KV tile 64. 8 warps, each owns 16 query rows.
// S = Q@K^T via mma; online softmax in fragment registers (exp2f, log2e
// folded into Q scale); P -> per-warp smem -> A-fragments; O += P@V via mma.
// smem (floats): Qs[128][68], Ks[64][68], Vs[64][72], Ps[128][68]
// ---------------------------------------------------------------------------
#define QSS 68
#define VSS 72
#define F_QS 0
#define F_KS (128 * QSS)
#define F_VS (F_KS + 64 * QSS)
#define F_PS (F_VS + 64 * VSS)
#define FLASH_SMEM ((F_PS + 128 * QSS) * 4)

__global__ void __launch_bounds__(256) flash_kernel(
    const float* __restrict__ q, const float* __restrict__ k,
    const float* __restrict__ v, float* __restrict__ out)
{
    extern __shared__ float sm[];
    float* Qs = sm + F_QS;
    float* Ks = sm + F_KS;
    float* Vs = sm + F_VS;
    float* Ps = sm + F_PS;

    const int tid  = threadIdx.x;
    const int wid  = tid >> 5;
    const int lane = tid & 31;
    const int lr   = lane >> 2;
    const int lc   = lane & 3;
    const int rm   = wid * 16;           // warp's query-row base in tile

    const int bh = blockIdx.y;
    const int b = bh >> 4;
    const int h = bh & 15;
    const int q0 = blockIdx.x * 128;
    const float qscale = 0.125f * 1.4426950408889634f;  // D^-1/2 * log2(e)

    // load Q tile (scaled)
    const float* qb = q + ((size_t)(b * Nn_ + q0)) * Cdim + h * Dd;
    #pragma unroll
    for (int i = 0; i < 8; i++) {
        const int idx = tid + i * 256;       // 2048 float4s
        const int r = idx >> 4;
        const int c = (idx & 15) << 2;
        float4 t4 = *(const float4*)(qb + (size_t)r * Cdim + c);
        t4.x *= qscale; t4.y *= qscale; t4.z *= qscale; t4.w *= qscale;
        *(float4*)&Qs[r * QSS + c] = t4;
    }

    float m0 = -1e30f, m1 = -1e30f, l0 = 0.f, l1 = 0.f;
    float oacc[8][4];
    #pragma unroll
    for (int nt = 0; nt < 8; nt++)
        #pragma unroll
        for (int r = 0; r < 4; r++) oacc[nt][r] = 0.f;

    for (int kv0 = 0; kv0 < Nn_; kv0 += 64) {
        __syncthreads();   // everyone done with previous K/V (and Qs ready)
        const float* kb = k + ((size_t)(b * Nn_ + kv0)) * Cdim + h * Dd;
        const float* vb = v + ((size_t)(b * Nn_ + kv0)) * Cdim + h * Dd;
        #pragma unroll
        for (int i = 0; i < 4; i++) {
            const int idx = tid + i * 256;   // 1024 float4s each
            const int r = idx >> 4;
            const int c = (idx & 15) << 2;
            *(float4*)&Ks[r * QSS + c] = *(const float4*)(kb + (size_t)r * Cdim + c);
            *(float4*)&Vs[r * VSS + c] = *(const float4*)(vb + (size_t)r * Cdim + c);
        }
        __syncthreads();

        // S = Qs @ Ks^T : warp computes rows [rm, rm+16), all 64 kv cols
        float sacc[8][4];
        #pragma unroll
        for (int nt = 0; nt < 8; nt++)
            #pragma unroll
            for (int r = 0; r < 4; r++) sacc[nt][r] = 0.f;
        #pragma unroll
        for (int ks = 0; ks < 8; ks++) {
            const int kk = ks * 8;
            uint32_t af[4];
            af[0] = __float_as_uint(Qs[(rm + lr) * QSS + kk + lc]);
            af[1] = __float_as_uint(Qs[(rm + lr + 8) * QSS + kk + lc]);
            af[2] = __float_as_uint(Qs[(rm + lr) * QSS + kk + lc + 4]);
            af[3] = __float_as_uint(Qs[(rm + lr + 8) * QSS + kk + lc + 4]);
            #pragma unroll
            for (int nt = 0; nt < 8; nt++) {
                uint32_t bf[2];
                bf[0] = __float_as_uint(Ks[(nt * 8 + lr) * QSS + kk + lc]);
                bf[1] = __float_as_uint(Ks[(nt * 8 + lr) * QSS + kk + lc + 4]);
                MMA_TF32(sacc[nt], af, bf);
            }
        }

        // online softmax. row0 = rm+lr (regs 0,1), row1 = rm+lr+8 (regs 2,3)
        float mx0 = -1e30f, mx1 = -1e30f;
        #pragma unroll
        for (int nt = 0; nt < 8; nt++) {
            mx0 = fmaxf(mx0, fmaxf(sacc[nt][0], sacc[nt][1]));
            mx1 = fmaxf(mx1, fmaxf(sacc[nt][2], sacc[nt][3]));
        }
        #pragma unroll
        for (int o = 1; o < 4; o <<= 1) {
            mx0 = fmaxf(mx0, __shfl_xor_sync(0xffffffffu, mx0, o, 4));
            mx1 = fmaxf(mx1, __shfl_xor_sync(0xffffffffu, mx1, o, 4));
        }
        const float mn0 = fmaxf(m0, mx0);
        const float mn1 = fmaxf(m1, mx1);
        const float al0 = exp2f(m0 - mn0);
        const float al1 = exp2f(m1 - mn1);
        float rs0 = 0.f, rs1 = 0.f;
        #pragma unroll
        for (int nt = 0; nt < 8; nt++) {
            const float p0 = exp2f(sacc[nt][0] - mn0);
            const float p1 = exp2f(sacc[nt][1] - mn0);
            const float p2 = exp2f(sacc[nt][2] - mn1);
            const float p3 = exp2f(sacc[nt][3] - mn1);
            rs0 += p0 + p1; rs1 += p2 + p3;
            *(float2*)&Ps[(rm + lr) * QSS + nt * 8 + 2 * lc]     = make_float2(p0, p1);
            *(float2*)&Ps[(rm + lr + 8) * QSS + nt * 8 + 2 * lc] = make_float2(p2, p3);
        }
        #pragma unroll
        for (int o = 1; o < 4; o <<= 1) {
            rs0 += __shfl_xor_sync(0xffffffffu, rs0, o, 4);
            rs1 += __shfl_xor_sync(0xffffffffu, rs1, o, 4);
        }
        l0 = l0 * al0 + rs0;  m0 = mn0;
        l1 = l1 * al1 + rs1;  m1 = mn1;
        #pragma unroll
        for (int nt = 0; nt < 8; nt++) {
            oacc[nt][0] *= al0; oacc[nt][1] *= al0;
            oacc[nt][2] *= al1; oacc[nt][3] *= al1;
        }
        __syncwarp();   // Ps rows are warp-private; make stores visible

        // O += P @ V : k over the 64 kv rows, n over D=64
        #pragma unroll
        for (int ks = 0; ks < 8; ks++) {
            const int kk = ks * 8;
            uint32_t af[4];
            af[0] = __float_as_uint(Ps[(rm + lr) * QSS + kk + lc]);
            af[1] = __float_as_uint(Ps[(rm + lr + 8) * QSS + kk + lc]);
            af[2] = __float_as_uint(Ps[(rm + lr) * QSS + kk + lc + 4]);
            af[3] = __float_as_uint(Ps[(rm + lr + 8) * QSS + kk + lc + 4]);
            #pragma unroll
            for (int nt = 0; nt < 8; nt++) {
                uint32_t bf[2];
                bf[0] = __float_as_uint(Vs[(kk + lc) * VSS + nt * 8 + lr]);
                bf[1] = __float_as_uint(Vs[(kk + lc + 4) * VSS + nt * 8 + lr]);
                MMA_TF32(oacc[nt], af, bf);
            }
        }
    }

    // write O / l
    const float il0 = 1.0f / l0;
    const float il1 = 1.0f / l1;
    float* ob = out + ((size_t)(b * Nn_ + q0 + rm)) * Cdim + h * Dd;
    #pragma unroll
    for (int nt = 0; nt < 8; nt++) {
        const int col = nt * 8 + 2 * lc;
        *(float2*)(ob + (size_t)lr * Cdim + col) =
            make_float2(oacc[nt][0] * il0, oacc[nt][1] * il0);
        *(float2*)(ob + (size_t)(lr + 8) * Cdim + col) =
            make_float2(oacc[nt][2] * il1, oacc[nt][3] * il1);
    }
}

// ---------------------------------------------------------------------------
extern "C" void kernel_launch(void* const* d_in, const int* in_sizes, int n_in,
                              void* d_out, int out_size)
{
    const float* x    = (const float*)d_in[0];
    const float* rcos = (const float*)d_in[1];
    const float* rsin = (const float*)d_in[2];
    const float* g1   = (const float*)d_in[3];
    const float* be1  = (const float*)d_in[4];
    const float* Wq   = (const float*)d_in[5];
    const float* bq   = (const float*)d_in[6];
    const float* Wk   = (const float*)d_in[7];
    const float* bk   = (const float*)d_in[8];
    const float* Wv   = (const float*)d_in[9];
    const float* bv   = (const float*)d_in[10];
    const float* Wo   = (const float*)d_in[11];
    const float* bo   = (const float*)d_in[12];
    const float* g2   = (const float*)d_in[13];
    const float* be2  = (const float*)d_in[14];
    const float* W1   = (const float*)d_in[15];
    const float* b1   = (const float*)d_in[16];
    const float* W2   = (const float*)d_in[17];
    const float* b2   = (const float*)d_in[18];
    float* out = (float*)d_out;

    float* base = nullptr;
    cudaGetSymbolAddress((void**)&base, g_scratch);
    float* p_h   = base + OFF_H;
    float* p_q   = base + OFF_Q;
    float* p_k   = base + OFF_K;
    float* p_v   = base + OFF_V;
    float* p_att = base + OFF_ATT;
    float* p_x2  = base + OFF_X2;
    float* p_mlp = base + OFF_MLP;

    cudaFuncSetAttribute(flash_kernel,
                         cudaFuncAttributeMaxDynamicSharedMemorySize, FLASH_SMEM);
    cudaFuncSetAttribute(tgemm_kernel,
                         cudaFuncAttributeMaxDynamicSharedMemorySize, GEMM_SMEM);

    // 1. LN1
    ln_kernel<<<Mrows, 256>>>(x, g1, be1, p_h);

    // 2. QKV projections
    dim3 gC(Cdim / 128, Mrows / 128);
    tgemm_kernel<<<gC, 256, GEMM_SMEM>>>(p_h, Wq, bq, nullptr, p_q, Mrows, Cdim, Cdim, 0);
    tgemm_kernel<<<gC, 256, GEMM_SMEM>>>(p_h, Wk, bk, nullptr, p_k, Mrows, Cdim, Cdim, 0);
    tgemm_kernel<<<gC, 256, GEMM_SMEM>>>(p_h, Wv, bv, nullptr, p_v, Mrows, Cdim, Cdim, 0);

    // 3. RoPE
    const int rblocks = (Bb * Nn_ * Hh * 32) / 256;
    rope_kernel<<<rblocks, 256>>>(p_q, rcos, rsin);
    rope_kernel<<<rblocks, 256>>>(p_k, rcos, rsin);

    // 4. attention (tensor cores)
    flash_kernel<<<dim3(Nn_ / 128, Bb * Hh), 256, FLASH_SMEM>>>(p_q, p_k, p_v, p_att);

    // 5. output projection + residual
    tgemm_kernel<<<gC, 256, GEMM_SMEM>>>(p_att, Wo, bo, x, p_x2, Mrows, Cdim, Cdim, 0);

    // 6. LN2
    ln_kernel<<<Mrows, 256>>>(p_x2, g2, be2, p_h);

    // 7. MLP up + GELU
    dim3 gF(Fdim / 128, Mrows / 128);
    tgemm_kernel<<<gF, 256, GEMM_SMEM>>>(p_h, W1, b1, nullptr, p_mlp, Mrows, Fdim, Cdim, 1);

    // 8. MLP down + residual -> output
    tgemm_kernel<<<gC, 256, GEMM_SMEM>>>(p_mlp, W2, b2, p_x2, out, Mrows, Cdim, Fdim, 0);
}